// round 4
// baseline (speedup 1.0000x reference)
#include <cuda_runtime.h>
#include <cstdint>

// ============================================================================
// out = dequant( fp8(x*xs) @ fp8(w^T*ws)^T ) * (1/xs)(1/ws)
//   x: [8,8192,512] f32 -> M=65536, K=512 ; w: [512,512] f32 -> N=512
// Pipeline: amax(x), amax(w) -> scales -> quantize x & w into pre-swizzled
// fp8 SMEM images -> mma.sync fp8 GEMM (base-ISA; NO tcgen05 — ptxas target
// is plain sm_103 and rejects all 'a'-gated instructions).
// ============================================================================

#define KDIM 512
#define NDIM 512
#define MDIM 65536
#define BM 64
#define BN 128
#define GEMM_THREADS 256

#define SMEM_A_OFF 0
#define SMEM_A_BYTES (BM * KDIM)              // 32768
#define SMEM_B_OFF SMEM_A_BYTES
#define SMEM_B_BYTES (BN * KDIM)              // 65536
#define SMEM_TOTAL (SMEM_A_BYTES + SMEM_B_BYTES)  // 98304

// ---------------------------------------------------------------------------
// device globals (static scratch; no runtime allocation)
// ---------------------------------------------------------------------------
__device__ unsigned int g_amax_x_bits;
__device__ unsigned int g_amax_w_bits;
__device__ float g_x_scale;
__device__ float g_w_scale;
__device__ float g_inv_combined;
// B image: per n-block (128 rows) the exact GEMM SMEM image:
//   offset = nb*65536 + row*512 + swz(granule, row) , row = n % 128
__device__ unsigned char g_wq[NDIM * KDIM];
// A image: per m-tile (64 rows) the exact GEMM SMEM image:
//   offset = tile*32768 + row*512 + swz(granule, row) , row = m % 64
__device__ unsigned char g_xq[(size_t)MDIM * KDIM];

// ---------------------------------------------------------------------------
// helpers
// ---------------------------------------------------------------------------
__device__ __forceinline__ uint32_t smem_u32(const void* p) {
    uint32_t a;
    asm("{ .reg .u64 t; cvta.to.shared.u64 t, %1; cvt.u32.u64 %0, t; }"
        : "=r"(a) : "l"(p));
    return a;
}

// 16B-granule swizzle within each row (row stride 512B):
// granule g (0..31) of row r lives at ((g ^ (r & 7)) << 4). Conflict-free for
// ldmatrix row-groups of 8 and for full-row STS.128.
__device__ __forceinline__ uint32_t swz(uint32_t g, uint32_t r) {
    return (g ^ (r & 7u)) << 4;
}

// pack two floats -> two e4m3 bytes (RN + saturate == reference clip+cast)
__device__ __forceinline__ uint32_t f2e4m3x2(float lo, float hi) {
    unsigned short v;
    asm("cvt.rn.satfinite.e4m3x2.f32 %0, %1, %2;" : "=h"(v) : "f"(hi), "f"(lo));
    return (uint32_t)v;
}

__device__ __forceinline__ unsigned char f2e4m3_one(float f) {
    unsigned short v;
    asm("cvt.rn.satfinite.e4m3x2.f32 %0, %1, %2;" : "=h"(v) : "f"(0.0f), "f"(f));
    return (unsigned char)(v & 0xFF);
}

__device__ __forceinline__ void ldsm_x4(uint32_t* r, uint32_t addr) {
    asm volatile(
        "ldmatrix.sync.aligned.m8n8.x4.shared.b16 {%0,%1,%2,%3}, [%4];"
        : "=r"(r[0]), "=r"(r[1]), "=r"(r[2]), "=r"(r[3]) : "r"(addr));
}

__device__ __forceinline__ void mma_e4m3(float* d, const uint32_t* a,
                                         uint32_t b0, uint32_t b1) {
    asm volatile(
        "mma.sync.aligned.m16n8k32.row.col.f32.e4m3.e4m3.f32 "
        "{%0,%1,%2,%3}, {%4,%5,%6,%7}, {%8,%9}, {%0,%1,%2,%3};"
        : "+f"(d[0]), "+f"(d[1]), "+f"(d[2]), "+f"(d[3])
        : "r"(a[0]), "r"(a[1]), "r"(a[2]), "r"(a[3]), "r"(b0), "r"(b1));
}

// ---------------------------------------------------------------------------
// kernel 1: reset amax accumulators
// ---------------------------------------------------------------------------
__global__ void init_kernel() {
    g_amax_x_bits = 0u;
    g_amax_w_bits = 0u;
}

// ---------------------------------------------------------------------------
// kernel 2: grid-stride |max| (nonneg floats: bit-max == float-max)
// ---------------------------------------------------------------------------
__global__ void amax_kernel(const float4* __restrict__ p, int n4, int which) {
    float m = 0.0f;
    for (int i = blockIdx.x * blockDim.x + threadIdx.x; i < n4;
         i += gridDim.x * blockDim.x) {
        float4 v = p[i];
        m = fmaxf(m, fmaxf(fmaxf(fabsf(v.x), fabsf(v.y)),
                           fmaxf(fabsf(v.z), fabsf(v.w))));
    }
    #pragma unroll
    for (int o = 16; o; o >>= 1) m = fmaxf(m, __shfl_xor_sync(0xffffffffu, m, o));
    __shared__ float wmax[8];
    int wid = threadIdx.x >> 5;
    if ((threadIdx.x & 31) == 0) wmax[wid] = m;
    __syncthreads();
    if (threadIdx.x < 8) {
        float mm = wmax[threadIdx.x];
        #pragma unroll
        for (int o = 4; o; o >>= 1) mm = fmaxf(mm, __shfl_xor_sync(0xffu, mm, o));
        if (threadIdx.x == 0) {
            atomicMax(which ? &g_amax_w_bits : &g_amax_x_bits,
                      __float_as_uint(mm));
        }
    }
}

// ---------------------------------------------------------------------------
// kernel 3: scales (IEEE ops so fast-math can't perturb quantization)
// ---------------------------------------------------------------------------
__global__ void scale_kernel() {
    float ax = __uint_as_float(g_amax_x_bits);
    float aw = __uint_as_float(g_amax_w_bits);
    float xsc = __fdiv_rn(448.0f, fmaxf(ax, 1e-12f));
    float wsc = __fdiv_rn(448.0f, fmaxf(aw, 1e-12f));
    g_x_scale = xsc;
    g_w_scale = wsc;
    g_inv_combined = __fmul_rn(__frcp_rn(xsc), __frcp_rn(wsc));
}

// ---------------------------------------------------------------------------
// kernel 4: quantize weight transposed: wq[n][k] = e4m3(w[k][n]*ws), stored
// as the GEMM's swizzled B SMEM image. 512x512 grid-exact launch.
// ---------------------------------------------------------------------------
__global__ void quant_w_kernel(const float* __restrict__ w) {
    int idx = blockIdx.x * blockDim.x + threadIdx.x;  // k*512 + n
    float ws = g_w_scale;
    int k = idx >> 9;
    int n = idx & 511;
    unsigned char b = f2e4m3_one(w[idx] * ws);
    uint32_t r = (uint32_t)(n & 127);
    uint32_t off = (uint32_t)(n >> 7) * 65536u + r * 512u +
                   swz((uint32_t)k >> 4, r) + (uint32_t)(k & 15);
    g_wq[off] = b;
}

// ---------------------------------------------------------------------------
// kernel 5: quantize activations into swizzled A SMEM images.
// One thread per 16-byte fp8 granule (reads 16 f32 = 64B).
// ---------------------------------------------------------------------------
__global__ void quant_x_kernel(const float* __restrict__ x) {
    uint32_t idx = blockIdx.x * blockDim.x + threadIdx.x;  // granule id
    uint32_t m = idx >> 5;
    uint32_t g = idx & 31;
    float xs = g_x_scale;
    const float4* p = reinterpret_cast<const float4*>(x + (size_t)m * KDIM + g * 16);
    float4 f0 = p[0], f1 = p[1], f2 = p[2], f3 = p[3];
    uint4 q;
    q.x = f2e4m3x2(f0.x * xs, f0.y * xs) | (f2e4m3x2(f0.z * xs, f0.w * xs) << 16);
    q.y = f2e4m3x2(f1.x * xs, f1.y * xs) | (f2e4m3x2(f1.z * xs, f1.w * xs) << 16);
    q.z = f2e4m3x2(f2.x * xs, f2.y * xs) | (f2e4m3x2(f2.z * xs, f2.w * xs) << 16);
    q.w = f2e4m3x2(f3.x * xs, f3.y * xs) | (f2e4m3x2(f3.z * xs, f3.w * xs) << 16);
    uint32_t row = m & 63u;
    size_t off = (size_t)(m >> 6) * 32768u + row * 512u + swz(g, row);
    *reinterpret_cast<uint4*>(g_xq + off) = q;
}

// ---------------------------------------------------------------------------
// kernel 6: FP8 GEMM via mma.sync m16n8k32 (QMMA), K=512 fully in SMEM.
// CTA: 64(M) x 128(N), 8 warps, warp tile 32x32. occupancy 2 (96KB smem).
// Grid (4, 1024), n-fast so 4 CTAs sharing an A tile are adjacent -> L2 reuse.
// ---------------------------------------------------------------------------
__global__ void __launch_bounds__(GEMM_THREADS, 2)
fp8_gemm_kernel(float* __restrict__ out) {
    extern __shared__ char smem[];
    const uint32_t sb = smem_u32(smem);
    const int tid = threadIdx.x;
    const int lid = tid & 31;
    const int wid = tid >> 5;
    const int wm = wid & 1;   // 2 m-subtiles of 32
    const int wn = wid >> 1;  // 4 n-subtiles of 32
    const int mt = blockIdx.y;       // m-tile (64 rows)
    const int nb = blockIdx.x;       // n-block (128 cols)

    // ---- load A image (linear 32KB) and B image (linear 64KB)
    {
        const uint4* sa = reinterpret_cast<const uint4*>(g_xq + (size_t)mt * 32768u);
        const uint4* sw = reinterpret_cast<const uint4*>(g_wq + nb * 65536u);
        uint4* da = reinterpret_cast<uint4*>(smem + SMEM_A_OFF);
        uint4* db = reinterpret_cast<uint4*>(smem + SMEM_B_OFF);
        #pragma unroll
        for (int i = 0; i < 8; i++) da[tid + i * GEMM_THREADS] = sa[tid + i * GEMM_THREADS];
        #pragma unroll
        for (int i = 0; i < 16; i++) db[tid + i * GEMM_THREADS] = sw[tid + i * GEMM_THREADS];
    }
    __syncthreads();

    // ---- per-lane ldmatrix base addresses
    // A m16 tile (per x4): lanes 0-15 -> rows 0..15 khalf0; 16-31 -> rows khalf1
    const uint32_t arow = (uint32_t)(wm * 32 + (lid & 15));
    const uint32_t ahalf = (uint32_t)(lid >> 4);
    const uint32_t abase = sb + SMEM_A_OFF + arow * 512u;
    // B n16 tile (per x4): lanes 0-7 rows n0..7 h0; 8-15 rows n0..7 h1;
    //                      16-23 rows n8..15 h0; 24-31 rows n8..15 h1
    const uint32_t brow = (uint32_t)(wn * 32 + (lid & 7) + ((lid & 16) >> 1));
    const uint32_t bhalf = (uint32_t)((lid >> 3) & 1);
    const uint32_t bbase = sb + SMEM_B_OFF + brow * 512u;
    const uint32_t lxor = (uint32_t)(lid & 7);

    float acc[2][4][4];
    #pragma unroll
    for (int i = 0; i < 2; i++)
        #pragma unroll
        for (int j = 0; j < 4; j++)
            #pragma unroll
            for (int c = 0; c < 4; c++) acc[i][j][c] = 0.0f;

    // ---- mainloop: 16 K-steps of 32
    #pragma unroll
    for (int ks = 0; ks < 16; ks++) {
        uint32_t a0[4], a1[4], b0[4], b1[4];
        uint32_t ga = ((uint32_t)(ks * 2) + ahalf) ^ lxor;
        uint32_t gb = ((uint32_t)(ks * 2) + bhalf) ^ lxor;
        ldsm_x4(a0, abase + (ga << 4));            // rows wm*32+0..15
        ldsm_x4(a1, abase + 16u * 512u + (ga << 4));  // rows +16..31 (same xor)
        ldsm_x4(b0, bbase + (gb << 4));            // n wn*32+0..15
        ldsm_x4(b1, bbase + 16u * 512u + (gb << 4));  // n +16..31
        mma_e4m3(acc[0][0], a0, b0[0], b0[1]);
        mma_e4m3(acc[0][1], a0, b0[2], b0[3]);
        mma_e4m3(acc[0][2], a0, b1[0], b1[1]);
        mma_e4m3(acc[0][3], a0, b1[2], b1[3]);
        mma_e4m3(acc[1][0], a1, b0[0], b0[1]);
        mma_e4m3(acc[1][1], a1, b0[2], b0[3]);
        mma_e4m3(acc[1][2], a1, b1[0], b1[1]);
        mma_e4m3(acc[1][3], a1, b1[2], b1[3]);
    }

    // ---- epilogue: dequant + coalesced float2 stores
    const float inv = g_inv_combined;
    const int qr = lid >> 2;
    const int qc = (lid & 3) * 2;
    const int m0 = mt * BM + wm * 32;
    const int n0 = nb * BN + wn * 32;
    #pragma unroll
    for (int tm = 0; tm < 2; tm++) {
        #pragma unroll
        for (int tn = 0; tn < 4; tn++) {
            const float* c = acc[tm][tn];
            size_t r0 = (size_t)(m0 + tm * 16 + qr) * NDIM + n0 + tn * 8 + qc;
            float2 v0 = make_float2(c[0] * inv, c[1] * inv);
            float2 v1 = make_float2(c[2] * inv, c[3] * inv);
            *reinterpret_cast<float2*>(out + r0) = v0;
            *reinterpret_cast<float2*>(out + r0 + (size_t)8 * NDIM) = v1;
        }
    }
}

// ---------------------------------------------------------------------------
// launch
// ---------------------------------------------------------------------------
extern "C" void kernel_launch(void* const* d_in, const int* in_sizes, int n_in,
                              void* d_out, int out_size) {
    const float* x = (const float*)d_in[0];
    const float* w = (const float*)d_in[1];
    float* out = (float*)d_out;

    init_kernel<<<1, 1>>>();
    amax_kernel<<<2048, 256>>>((const float4*)x, (MDIM * KDIM) / 4, 0);
    amax_kernel<<<128, 256>>>((const float4*)w, (KDIM * NDIM) / 4, 1);
    scale_kernel<<<1, 1>>>();
    quant_w_kernel<<<512, 512>>>(w);
    quant_x_kernel<<<(MDIM * (KDIM / 16)) / 256, 256>>>(x);

    cudaFuncSetAttribute(fp8_gemm_kernel,
                         cudaFuncAttributeMaxDynamicSharedMemorySize,
                         SMEM_TOTAL);
    dim3 grid(NDIM / BN, MDIM / BM);  // (4, 1024), n-fast for A reuse in L2
    fp8_gemm_kernel<<<grid, GEMM_THREADS, SMEM_TOTAL>>>(out);
}